// round 13
// baseline (speedup 1.0000x reference)
#include <cuda_runtime.h>

typedef unsigned long long u64;

#define LOG2E 1.4426950408889634f
#define LN2   0.6931471805599453f
#define B    512
#define TT   1024
#define L    48
#define RING 16   // cp.async emission ring slots (192B each)

__device__ float g_fwd[B];
__device__ float g_gold[B];

static __device__ __forceinline__ u64 pk2(float lo, float hi){ u64 r; asm("mov.b64 %0, {%1, %2};" : "=l"(r) : "f"(lo), "f"(hi)); return r; }
static __device__ __forceinline__ void upk2(u64 v, float& lo, float& hi){ asm("mov.b64 {%0, %1}, %2;" : "=f"(lo), "=f"(hi) : "l"(v)); }
static __device__ __forceinline__ u64 fma2(u64 a, u64 b, u64 c){ u64 d; asm("fma.rn.f32x2 %0, %1, %2, %3;" : "=l"(d) : "l"(a), "l"(b), "l"(c)); return d; }
static __device__ __forceinline__ u64 mul2(u64 a, u64 b){ u64 d; asm("mul.rn.f32x2 %0, %1, %2;" : "=l"(d) : "l"(a), "l"(b)); return d; }
static __device__ __forceinline__ u64 add2(u64 a, u64 b){ u64 d; asm("add.rn.f32x2 %0, %1, %2;" : "=l"(d) : "l"(a), "l"(b)); return d; }
static __device__ __forceinline__ float ex2f(float x){ float y; asm("ex2.approx.ftz.f32 %0, %1;" : "=f"(y) : "f"(x)); return y; }
static __device__ __forceinline__ float lg2f(float x){ float y; asm("lg2.approx.ftz.f32 %0, %1;" : "=f"(y) : "f"(x)); return y; }
static __device__ __forceinline__ unsigned smem_u32(const void* p){
    unsigned a; asm("{ .reg .u64 t; cvta.to.shared.u64 t, %1; cvt.u32.u64 %0, t; }" : "=r"(a) : "l"(p)); return a; }

// ---------------------------------------------------------------------------
// Forward kernel: 512 blocks x 32 threads — one warp per sequence (R12 base).
// Changes vs R12 (302 cyc/step, ~180 of it stall):
//  1. cp.async.wait_group amortized: one predicated DEPBAR per 8 steps
//     (count 7), instead of per-step count 14. Group math: at step t,
//     committed = t+14; waiting 7 leaves rows <= t+7 resident.
//  2. Emission LDS + ex2f + mask word hoisted ABOVE the matvec — their
//     29+16 cyc latency now overlaps the FMA2 stream instead of serializing
//     on the dot's tail.
// All else identical: dup-layout STS.128 state exchange, ballot mask bits,
// exact pow-2 renorm every 4 steps, syncwarp-only synchronization.
// ---------------------------------------------------------------------------
__global__ __launch_bounds__(32, 1) void crf_fwd_kernel(
    const float* __restrict__ em, const int* __restrict__ mask,
    const float* __restrict__ trans, const float* __restrict__ startt,
    const float* __restrict__ endt)
{
    __shared__ __align__(16) float udup[2][128];      // dup state ping-pong
    __shared__ __align__(16) float ring[RING * 48];   // emission ring (3KB)
    __shared__ unsigned mb[32];                       // mask bits (1024 steps)

    const int lane = threadIdx.x;
    const int i  = lane < 24 ? lane : 23;             // clamp shadow lanes
    const int b  = blockIdx.x;
    const int j0 = 2 * i, j1 = 2 * i + 1;

    // ---- mask bits via ballot ----
    #pragma unroll 1
    for (int k = 0; k < 32; k++) {
        int v = mask[b * TT + k * 32 + lane];
        unsigned w = __ballot_sync(0xFFFFFFFFu, v != 0);
        if (lane == k) mb[k] = w;
    }

    // ---- transition columns (j0, j1), exponentiated, packed (48 u64) ----
    u64 et[L];
    #pragma unroll
    for (int k = 0; k < L; k++) {
        float e0 = ex2f(trans[k * L + j0] * LOG2E);
        float e1 = ex2f(trans[k * L + j1] * LOG2E);
        et[k] = pk2(e0, e1);
    }
    const float eEnd0 = ex2f(endt[j0] * LOG2E);
    const float eEnd1 = ex2f(endt[j1] * LOG2E);

    // ---- initial state u0 = exp(start + em[0]) ----
    u64 res;
    {
        float a = ex2f((startt[j0] + em[(size_t)b * TT * L + j0]) * LOG2E);
        float c = ex2f((startt[j1] + em[(size_t)b * TT * L + j1]) * LOG2E);
        res = pk2(a, c);
        float lo, hi; upk2(res, lo, hi);
        reinterpret_cast<float4*>(&udup[0][0])[lane] = make_float4(lo, lo, hi, hi);
    }

    // ---- cp.async ring prologue: lanes 0..11 copy 16B each (48 floats/row) ----
    const float* gsrc = em + (size_t)b * TT * L + lane * 4;
    const unsigned ring_base = smem_u32(&ring[0]);
    const unsigned dst_off = (unsigned)(lane * 16);
    for (int tp = 1; tp < RING; ++tp) {
        if (lane < 12) {
            const float* src = gsrc + (size_t)tp * L;
            unsigned d = ring_base + (unsigned)tp * 192u + dst_off;
            asm volatile("cp.async.cg.shared.global [%0], [%1], 16;" :: "r"(d), "l"(src));
        }
        asm volatile("cp.async.commit_group;");
    }
    asm volatile("cp.async.wait_group 7;");   // rows 1..8 resident
    __syncwarp();

    int iA = 0;   // exact integer log2 credit
    const ulonglong2* rd = reinterpret_cast<const ulonglong2*>(&udup[0][0]);
    float4*           wr = reinterpret_cast<float4*>(&udup[1][0]);

    #pragma unroll 1
    for (int t = 1; t < TT; ++t) {
        // ---- amortized ring wait: one DEPBAR per 8 steps covers t..t+7 ----
        if ((t & 7) == 1)
            asm volatile("cp.async.wait_group 7;");

        // ---- hoisted: emission pair + mask bit (independent of u state) ----
        const int slot = t & (RING - 1);
        u64 emp = *reinterpret_cast<const u64*>(&ring[slot * 48 + j0]);
        float emLo, emHi; upk2(emp, emLo, emHi);
        u64 Ee = pk2(ex2f(emLo * LOG2E), ex2f(emHi * LOG2E));
        bool mbit = (mb[t >> 5] >> (t & 31)) & 1u;

        // ---- 48x48 matvec: 24 broadcast LDS.128, 48 FMA2 into 4 accums ----
        u64 a0 = 0, a1 = 0, a2 = 0, a3 = 0;
        u64 first = 0;
        #pragma unroll
        for (int q = 0; q < 12; q++) {
            ulonglong2 wA = rd[2 * q];        // (splat u_{4q},   splat u_{4q+1})
            ulonglong2 wB = rd[2 * q + 1];    // (splat u_{4q+2}, splat u_{4q+3})
            if (q == 0) first = wA.x;
            a0 = fma2(wA.x, et[4 * q + 0], a0);
            a1 = fma2(wA.y, et[4 * q + 1], a1);
            a2 = fma2(wB.x, et[4 * q + 2], a2);
            a3 = fma2(wB.y, et[4 * q + 3], a3);
        }
        u64 dot = add2(add2(a0, a1), add2(a2, a3));

        u64 prod = mul2(dot, Ee);
        u64 sel = mbit ? prod : res;

        if ((t & 3) == 0) {                   // exact power-of-2 renorm (from u[0])
            unsigned eb = (unsigned)first & 0x7F800000u;
            float f = __uint_as_float(0x7F000000u - eb);
            sel = mul2(sel, pk2(f, f));
            iA += (int)(eb >> 23) - 127;
        }
        res = sel;

        // ---- publish new state (dup layout, one STS.128) ----
        float lo, hi; upk2(res, lo, hi);
        wr[lane] = make_float4(lo, lo, hi, hi);

        // ---- refill ring slot for row t+15 (clamped) ----
        {
            int tf = t + (RING - 1); if (tf > TT - 1) tf = TT - 1;
            if (lane < 12) {
                const float* src = gsrc + (size_t)tf * L;
                unsigned d = ring_base + (unsigned)(tf & (RING - 1)) * 192u + dst_off;
                asm volatile("cp.async.cg.shared.global [%0], [%1], 16;" :: "r"(d), "l"(src));
            }
            asm volatile("cp.async.commit_group;");
        }

        // swap ping-pong
        float4* nw = (float4*)rd;
        rd = (const ulonglong2*)wr;
        wr = nw;

        __syncwarp();
    }

    // ---- finalize: logZ = (log2(sum_j u_j * expEnd_j) + credit) * ln2 ----
    float lo, hi; upk2(res, lo, hi);
    float s = (lane < 24) ? (lo * eEnd0 + hi * eEnd1) : 0.f;
    #pragma unroll
    for (int o = 16; o > 0; o >>= 1) s += __shfl_down_sync(0xFFFFFFFFu, s, o);
    if (lane == 0) g_fwd[b] = (lg2f(s) + (float)iA) * LN2;
}

// ---------------------------------------------------------------------------
// Gold score kernel: one block per batch element.
// ---------------------------------------------------------------------------
__global__ __launch_bounds__(256, 4) void crf_gold_kernel(
    const float* __restrict__ em, const int* __restrict__ labels,
    const int* __restrict__ mask, const float* __restrict__ trans,
    const float* __restrict__ startt, const float* __restrict__ endt)
{
    __shared__ float red[256];
    __shared__ int   redc[256];
    const int b = blockIdx.x;
    const int tid = threadIdx.x;

    float acc = 0.f;
    int cnt = 0;
    for (int t = tid; t < TT; t += 256) {
        int l = labels[b * TT + t];
        int m = mask[b * TT + t];
        cnt += m;
        float e = em[((size_t)(b * TT) + t) * L + l];
        if (t == 0) {
            acc += startt[l] + e;
        } else {
            int lp = labels[b * TT + t - 1];
            acc += (e + trans[l * L + lp]) * (float)m;
        }
    }
    red[tid] = acc; redc[tid] = cnt;
    __syncthreads();
    for (int s = 128; s > 0; s >>= 1) {
        if (tid < s) { red[tid] += red[tid + s]; redc[tid] += redc[tid + s]; }
        __syncthreads();
    }
    if (tid == 0) {
        int len = redc[0] - 1;
        int last = labels[b * TT + len];
        g_gold[b] = red[0] + endt[last];
    }
}

// ---------------------------------------------------------------------------
// Final reduction: mean(fwd - gold)
// ---------------------------------------------------------------------------
__global__ __launch_bounds__(512, 1) void crf_final_kernel(float* __restrict__ out)
{
    __shared__ float red[512];
    int tid = threadIdx.x;
    red[tid] = g_fwd[tid] - g_gold[tid];
    __syncthreads();
    for (int s = 256; s > 0; s >>= 1) {
        if (tid < s) red[tid] += red[tid + s];
        __syncthreads();
    }
    if (tid == 0) out[0] = red[0] * (1.0f / (float)B);
}

extern "C" void kernel_launch(void* const* d_in, const int* in_sizes, int n_in,
                              void* d_out, int out_size)
{
    const float* em     = (const float*)d_in[0];
    const int*   labels = (const int*)  d_in[1];
    const int*   mask   = (const int*)  d_in[2];
    const float* trans  = (const float*)d_in[3];
    const float* startt = (const float*)d_in[4];
    const float* endt   = (const float*)d_in[5];
    float* out = (float*)d_out;

    crf_fwd_kernel<<<B, 32>>>(em, mask, trans, startt, endt);
    crf_gold_kernel<<<B, 256>>>(em, labels, mask, trans, startt, endt);
    crf_final_kernel<<<1, 512>>>(out);
}

// round 14
// speedup vs baseline: 1.0646x; 1.0646x over previous
#include <cuda_runtime.h>

typedef unsigned long long u64;

#define LOG2E 1.4426950408889634f
#define LN2   0.6931471805599453f
#define B    512
#define TT   1024
#define L    48
#define RING 16   // cp.async emission ring slots (192B each)

__device__ float g_fwd[B];
__device__ float g_gold[B];

static __device__ __forceinline__ u64 pk2(float lo, float hi){ u64 r; asm("mov.b64 %0, {%1, %2};" : "=l"(r) : "f"(lo), "f"(hi)); return r; }
static __device__ __forceinline__ void upk2(u64 v, float& lo, float& hi){ asm("mov.b64 {%0, %1}, %2;" : "=f"(lo), "=f"(hi) : "l"(v)); }
static __device__ __forceinline__ u64 fma2(u64 a, u64 b, u64 c){ u64 d; asm("fma.rn.f32x2 %0, %1, %2, %3;" : "=l"(d) : "l"(a), "l"(b), "l"(c)); return d; }
static __device__ __forceinline__ u64 mul2(u64 a, u64 b){ u64 d; asm("mul.rn.f32x2 %0, %1, %2;" : "=l"(d) : "l"(a), "l"(b)); return d; }
static __device__ __forceinline__ u64 add2(u64 a, u64 b){ u64 d; asm("add.rn.f32x2 %0, %1, %2;" : "=l"(d) : "l"(a), "l"(b)); return d; }
static __device__ __forceinline__ float ex2f(float x){ float y; asm("ex2.approx.ftz.f32 %0, %1;" : "=f"(y) : "f"(x)); return y; }
static __device__ __forceinline__ float lg2f(float x){ float y; asm("lg2.approx.ftz.f32 %0, %1;" : "=f"(y) : "f"(x)); return y; }
static __device__ __forceinline__ unsigned smem_u32(const void* p){
    unsigned a; asm("{ .reg .u64 t; cvta.to.shared.u64 t, %1; cvt.u32.u64 %0, t; }" : "=r"(a) : "l"(p)); return a; }

// Predicated cp.async: no C++ branch, no BSSY/BSYNC — the guard lives in a
// setp + @p on the instruction itself.
static __device__ __forceinline__ void cp_async_16_pred(unsigned dst, const float* src, int pred){
    asm volatile(
        "{\n\t"
        ".reg .pred p;\n\t"
        "setp.ne.s32 p, %2, 0;\n\t"
        "@p cp.async.cg.shared.global [%0], [%1], 16;\n\t"
        "}"
        :: "r"(dst), "l"(src), "r"(pred));
}

// ---------------------------------------------------------------------------
// Forward kernel: 512 blocks x 32 threads — one warp per sequence (R12 base,
// 163.9us). R14 change: remove BOTH per-step C++ branches from the loop —
// each compiled to a BSSY/BSYNC pair (33-56 cyc/step each, per SASS_PATTERNS:
// ptxas never emits 0-BSSY predicated arms from C++ if{}):
//  1. renorm -> branchless: f = rn ? 2^(127-e) : 1.0 via SEL; one always-on
//     mul2 (exact when x1.0) replaces the branch.
//  2. cp.async lane guard -> @p predicated instruction inside asm.
// All else identical to R12: dup-layout STS.128 state exchange, per-step
// wait_group 14, ballot mask bits, syncwarp-only synchronization.
// ---------------------------------------------------------------------------
__global__ __launch_bounds__(32, 1) void crf_fwd_kernel(
    const float* __restrict__ em, const int* __restrict__ mask,
    const float* __restrict__ trans, const float* __restrict__ startt,
    const float* __restrict__ endt)
{
    __shared__ __align__(16) float udup[2][128];      // dup state ping-pong
    __shared__ __align__(16) float ring[RING * 48];   // emission ring (3KB)
    __shared__ unsigned mb[32];                       // mask bits (1024 steps)

    const int lane = threadIdx.x;
    const int i  = lane < 24 ? lane : 23;             // clamp shadow lanes
    const int b  = blockIdx.x;
    const int j0 = 2 * i, j1 = 2 * i + 1;
    const int isLd = (lane < 12) ? 1 : 0;             // cp.async lane predicate

    // ---- mask bits via ballot ----
    #pragma unroll 1
    for (int k = 0; k < 32; k++) {
        int v = mask[b * TT + k * 32 + lane];
        unsigned w = __ballot_sync(0xFFFFFFFFu, v != 0);
        if (lane == k) mb[k] = w;
    }

    // ---- transition columns (j0, j1), exponentiated, packed (48 u64) ----
    u64 et[L];
    #pragma unroll
    for (int k = 0; k < L; k++) {
        float e0 = ex2f(trans[k * L + j0] * LOG2E);
        float e1 = ex2f(trans[k * L + j1] * LOG2E);
        et[k] = pk2(e0, e1);
    }
    const float eEnd0 = ex2f(endt[j0] * LOG2E);
    const float eEnd1 = ex2f(endt[j1] * LOG2E);

    // ---- initial state u0 = exp(start + em[0]) ----
    u64 res;
    {
        float a = ex2f((startt[j0] + em[(size_t)b * TT * L + j0]) * LOG2E);
        float c = ex2f((startt[j1] + em[(size_t)b * TT * L + j1]) * LOG2E);
        res = pk2(a, c);
        float lo, hi; upk2(res, lo, hi);
        reinterpret_cast<float4*>(&udup[0][0])[lane] = make_float4(lo, lo, hi, hi);
    }

    // ---- cp.async ring prologue: lanes 0..11 copy 16B each (48 floats/row) ----
    const float* gsrc = em + (size_t)b * TT * L + lane * 4;
    const unsigned ring_base = smem_u32(&ring[0]);
    const unsigned dst_off = (unsigned)(lane * 16);
    for (int tp = 1; tp < RING; ++tp) {
        cp_async_16_pred(ring_base + (unsigned)tp * 192u + dst_off,
                         gsrc + (size_t)tp * L, isLd);
        asm volatile("cp.async.commit_group;");
    }
    asm volatile("cp.async.wait_group 14;");
    __syncwarp();

    int iA = 0;   // exact integer log2 credit
    const ulonglong2* rd = reinterpret_cast<const ulonglong2*>(&udup[0][0]);
    float4*           wr = reinterpret_cast<float4*>(&udup[1][0]);

    #pragma unroll 1
    for (int t = 1; t < TT; ++t) {
        // ---- 48x48 matvec: 24 broadcast LDS.128, 48 FMA2 into 4 accums ----
        u64 a0 = 0, a1 = 0, a2 = 0, a3 = 0;
        u64 first = 0;
        #pragma unroll
        for (int q = 0; q < 12; q++) {
            ulonglong2 wA = rd[2 * q];        // (splat u_{4q},   splat u_{4q+1})
            ulonglong2 wB = rd[2 * q + 1];    // (splat u_{4q+2}, splat u_{4q+3})
            if (q == 0) first = wA.x;
            a0 = fma2(wA.x, et[4 * q + 0], a0);
            a1 = fma2(wA.y, et[4 * q + 1], a1);
            a2 = fma2(wB.x, et[4 * q + 2], a2);
            a3 = fma2(wB.y, et[4 * q + 3], a3);
        }
        u64 dot = add2(add2(a0, a1), add2(a2, a3));

        // ---- emissions from ring + uniform mask bit ----
        const int slot = t & (RING - 1);
        u64 emp = *reinterpret_cast<const u64*>(&ring[slot * 48 + j0]);
        float emLo, emHi; upk2(emp, emLo, emHi);
        u64 Ee   = pk2(ex2f(emLo * LOG2E), ex2f(emHi * LOG2E));
        u64 prod = mul2(dot, Ee);
        bool mbit = (mb[t >> 5] >> (t & 31)) & 1u;
        u64 sel = mbit ? prod : res;

        // ---- branchless exact power-of-2 renorm (SEL, no BSSY) ----
        {
            int rn = (t & 3) == 0;
            unsigned eb = (unsigned)first & 0x7F800000u;
            float f = rn ? __uint_as_float(0x7F000000u - eb) : 1.0f;
            sel = mul2(sel, pk2(f, f));        // exact when f == 1.0
            iA += rn ? ((int)(eb >> 23) - 127) : 0;
        }
        res = sel;

        // ---- publish new state (dup layout, one STS.128) ----
        float lo, hi; upk2(res, lo, hi);
        wr[lane] = make_float4(lo, lo, hi, hi);

        // ---- refill ring slot for row t+15 (clamped; @p predicated) ----
        {
            int tf = t + (RING - 1); if (tf > TT - 1) tf = TT - 1;
            cp_async_16_pred(ring_base + (unsigned)(tf & (RING - 1)) * 192u + dst_off,
                             gsrc + (size_t)tf * L, isLd);
            asm volatile("cp.async.commit_group;");
            asm volatile("cp.async.wait_group 14;");   // row t+1 resident
        }

        // swap ping-pong
        float4* nw = (float4*)rd;
        rd = (const ulonglong2*)wr;
        wr = nw;

        __syncwarp();
    }

    // ---- finalize: logZ = (log2(sum_j u_j * expEnd_j) + credit) * ln2 ----
    float lo, hi; upk2(res, lo, hi);
    float s = (lane < 24) ? (lo * eEnd0 + hi * eEnd1) : 0.f;
    #pragma unroll
    for (int o = 16; o > 0; o >>= 1) s += __shfl_down_sync(0xFFFFFFFFu, s, o);
    if (lane == 0) g_fwd[b] = (lg2f(s) + (float)iA) * LN2;
}

// ---------------------------------------------------------------------------
// Gold score kernel: one block per batch element.
// ---------------------------------------------------------------------------
__global__ __launch_bounds__(256, 4) void crf_gold_kernel(
    const float* __restrict__ em, const int* __restrict__ labels,
    const int* __restrict__ mask, const float* __restrict__ trans,
    const float* __restrict__ startt, const float* __restrict__ endt)
{
    __shared__ float red[256];
    __shared__ int   redc[256];
    const int b = blockIdx.x;
    const int tid = threadIdx.x;

    float acc = 0.f;
    int cnt = 0;
    for (int t = tid; t < TT; t += 256) {
        int l = labels[b * TT + t];
        int m = mask[b * TT + t];
        cnt += m;
        float e = em[((size_t)(b * TT) + t) * L + l];
        if (t == 0) {
            acc += startt[l] + e;
        } else {
            int lp = labels[b * TT + t - 1];
            acc += (e + trans[l * L + lp]) * (float)m;
        }
    }
    red[tid] = acc; redc[tid] = cnt;
    __syncthreads();
    for (int s = 128; s > 0; s >>= 1) {
        if (tid < s) { red[tid] += red[tid + s]; redc[tid] += redc[tid + s]; }
        __syncthreads();
    }
    if (tid == 0) {
        int len = redc[0] - 1;
        int last = labels[b * TT + len];
        g_gold[b] = red[0] + endt[last];
    }
}

// ---------------------------------------------------------------------------
// Final reduction: mean(fwd - gold)
// ---------------------------------------------------------------------------
__global__ __launch_bounds__(512, 1) void crf_final_kernel(float* __restrict__ out)
{
    __shared__ float red[512];
    int tid = threadIdx.x;
    red[tid] = g_fwd[tid] - g_gold[tid];
    __syncthreads();
    for (int s = 256; s > 0; s >>= 1) {
        if (tid < s) red[tid] += red[tid + s];
        __syncthreads();
    }
    if (tid == 0) out[0] = red[0] * (1.0f / (float)B);
}

extern "C" void kernel_launch(void* const* d_in, const int* in_sizes, int n_in,
                              void* d_out, int out_size)
{
    const float* em     = (const float*)d_in[0];
    const int*   labels = (const int*)  d_in[1];
    const int*   mask   = (const int*)  d_in[2];
    const float* trans  = (const float*)d_in[3];
    const float* startt = (const float*)d_in[4];
    const float* endt   = (const float*)d_in[5];
    float* out = (float*)d_out;

    crf_fwd_kernel<<<B, 32>>>(em, mask, trans, startt, endt);
    crf_gold_kernel<<<B, 256>>>(em, labels, mask, trans, startt, endt);
    crf_final_kernel<<<1, 512>>>(out);
}

// round 15
// speedup vs baseline: 1.1323x; 1.0635x over previous
#include <cuda_runtime.h>

typedef unsigned long long u64;

#define LOG2E 1.4426950408889634f
#define LN2   0.6931471805599453f
#define B    512
#define TT   1024
#define L    48
#define RING 16   // cp.async emission ring slots (192B each)

__device__ float g_fwd[B];
__device__ float g_gold[B];

static __device__ __forceinline__ u64 pk2(float lo, float hi){ u64 r; asm("mov.b64 %0, {%1, %2};" : "=l"(r) : "f"(lo), "f"(hi)); return r; }
static __device__ __forceinline__ void upk2(u64 v, float& lo, float& hi){ asm("mov.b64 {%0, %1}, %2;" : "=f"(lo), "=f"(hi) : "l"(v)); }
static __device__ __forceinline__ u64 fma2(u64 a, u64 b, u64 c){ u64 d; asm("fma.rn.f32x2 %0, %1, %2, %3;" : "=l"(d) : "l"(a), "l"(b), "l"(c)); return d; }
static __device__ __forceinline__ u64 mul2(u64 a, u64 b){ u64 d; asm("mul.rn.f32x2 %0, %1, %2;" : "=l"(d) : "l"(a), "l"(b)); return d; }
static __device__ __forceinline__ u64 add2(u64 a, u64 b){ u64 d; asm("add.rn.f32x2 %0, %1, %2;" : "=l"(d) : "l"(a), "l"(b)); return d; }
static __device__ __forceinline__ float ex2f(float x){ float y; asm("ex2.approx.ftz.f32 %0, %1;" : "=f"(y) : "f"(x)); return y; }
static __device__ __forceinline__ float lg2f(float x){ float y; asm("lg2.approx.ftz.f32 %0, %1;" : "=f"(y) : "f"(x)); return y; }
static __device__ __forceinline__ unsigned smem_u32(const void* p){
    unsigned a; asm("{ .reg .u64 t; cvta.to.shared.u64 t, %1; cvt.u32.u64 %0, t; }" : "=r"(a) : "l"(p)); return a; }

// Predicated cp.async: guard via setp + @p, no divergent branch.
static __device__ __forceinline__ void cp_async_16_pred(unsigned dst, const float* src, int pred){
    asm volatile(
        "{\n\t"
        ".reg .pred p;\n\t"
        "setp.ne.s32 p, %2, 0;\n\t"
        "@p cp.async.cg.shared.global [%0], [%1], 16;\n\t"
        "}"
        :: "r"(dst), "l"(src), "r"(pred));
}

// ---------------------------------------------------------------------------
// Forward kernel: 512 blocks x 32 threads — one warp per sequence.
// R15 change vs the 163.9us baseline: STATIC UNROLL-4 of the time loop.
//  - ONE cp.async.wait_group 11 per 4 steps (committed=tb+14 at iter top;
//    pending<=11 => rows <= tb+3 resident). Replaces 4 DEPBARs.
//  - renorm at compile-time position (t % 4 == 0 => unroll offset 3):
//    its ops exist in 1 of 4 step bodies only.
//  - ping-pong buffers statically alternated; loop overhead /4.
// No conditional control flow added (the R13 failure mode).
// ---------------------------------------------------------------------------
__global__ __launch_bounds__(32, 1) void crf_fwd_kernel(
    const float* __restrict__ em, const int* __restrict__ mask,
    const float* __restrict__ trans, const float* __restrict__ startt,
    const float* __restrict__ endt)
{
    __shared__ __align__(16) float udup[2][128];      // dup state ping-pong
    __shared__ __align__(16) float ring[RING * 48];   // emission ring (3KB)
    __shared__ unsigned mb[32];                       // mask bits (1024 steps)

    const int lane = threadIdx.x;
    const int i  = lane < 24 ? lane : 23;             // clamp shadow lanes
    const int b  = blockIdx.x;
    const int j0 = 2 * i, j1 = 2 * i + 1;
    const int isLd = (lane < 12) ? 1 : 0;             // cp.async lane predicate

    // ---- mask bits via ballot ----
    #pragma unroll 1
    for (int k = 0; k < 32; k++) {
        int v = mask[b * TT + k * 32 + lane];
        unsigned w = __ballot_sync(0xFFFFFFFFu, v != 0);
        if (lane == k) mb[k] = w;
    }

    // ---- transition columns (j0, j1), exponentiated, packed (48 u64) ----
    u64 et[L];
    #pragma unroll
    for (int k = 0; k < L; k++) {
        float e0 = ex2f(trans[k * L + j0] * LOG2E);
        float e1 = ex2f(trans[k * L + j1] * LOG2E);
        et[k] = pk2(e0, e1);
    }
    const float eEnd0 = ex2f(endt[j0] * LOG2E);
    const float eEnd1 = ex2f(endt[j1] * LOG2E);

    // ---- initial state u0 = exp(start + em[0]) ----
    u64 res;
    {
        float a = ex2f((startt[j0] + em[(size_t)b * TT * L + j0]) * LOG2E);
        float c = ex2f((startt[j1] + em[(size_t)b * TT * L + j1]) * LOG2E);
        res = pk2(a, c);
        float lo, hi; upk2(res, lo, hi);
        reinterpret_cast<float4*>(&udup[0][0])[lane] = make_float4(lo, lo, hi, hi);
    }

    // ---- cp.async ring prologue: lanes 0..11 copy 16B each (48 floats/row) ----
    const float* gsrc = em + (size_t)b * TT * L + lane * 4;
    const unsigned ring_base = smem_u32(&ring[0]);
    const unsigned dst_off = (unsigned)(lane * 16);
    for (int tp = 1; tp < RING; ++tp) {
        cp_async_16_pred(ring_base + (unsigned)tp * 192u + dst_off,
                         gsrc + (size_t)tp * L, isLd);
        asm volatile("cp.async.commit_group;");
    }
    __syncwarp();

    int iA = 0;   // exact integer log2 credit

    // One step: reads RD_ (u[t-1] dup), writes WR_, updates res/iA.
    // RN_ is a compile-time constant — renorm ops exist only where true.
    #define STEP(T_, RD_, WR_, RN_)                                            \
    do {                                                                       \
        const int t_ = (T_);                                                   \
        const ulonglong2* rd_ = reinterpret_cast<const ulonglong2*>(RD_);      \
        u64 a0 = 0, a1 = 0, a2 = 0, a3 = 0;                                    \
        u64 first_ = 0;                                                        \
        _Pragma("unroll")                                                      \
        for (int q = 0; q < 12; q++) {                                         \
            ulonglong2 wA = rd_[2 * q];                                        \
            ulonglong2 wB = rd_[2 * q + 1];                                    \
            if (RN_ && q == 0) first_ = wA.x;                                  \
            a0 = fma2(wA.x, et[4 * q + 0], a0);                                \
            a1 = fma2(wA.y, et[4 * q + 1], a1);                                \
            a2 = fma2(wB.x, et[4 * q + 2], a2);                                \
            a3 = fma2(wB.y, et[4 * q + 3], a3);                                \
        }                                                                      \
        u64 dot = add2(add2(a0, a1), add2(a2, a3));                            \
        const int slot_ = t_ & (RING - 1);                                     \
        u64 emp = *reinterpret_cast<const u64*>(&ring[slot_ * 48 + j0]);       \
        float emLo_, emHi_; upk2(emp, emLo_, emHi_);                           \
        u64 Ee = pk2(ex2f(emLo_ * LOG2E), ex2f(emHi_ * LOG2E));                \
        u64 prod = mul2(dot, Ee);                                              \
        bool mbit_ = (mb[t_ >> 5] >> (t_ & 31)) & 1u;                          \
        u64 sel = mbit_ ? prod : res;                                          \
        if (RN_) {                                                             \
            unsigned eb_ = (unsigned)first_ & 0x7F800000u;                     \
            float f_ = __uint_as_float(0x7F000000u - eb_);                     \
            sel = mul2(sel, pk2(f_, f_));                                      \
            iA += (int)(eb_ >> 23) - 127;                                      \
        }                                                                      \
        res = sel;                                                             \
        float lo_, hi_; upk2(res, lo_, hi_);                                   \
        reinterpret_cast<float4*>(WR_)[lane] = make_float4(lo_, lo_, hi_, hi_);\
        int tf_ = t_ + (RING - 1); if (tf_ > TT - 1) tf_ = TT - 1;             \
        cp_async_16_pred(ring_base + (unsigned)((tf_ & (RING - 1)) * 192)      \
                         + dst_off, gsrc + (size_t)tf_ * L, isLd);             \
        asm volatile("cp.async.commit_group;");                                \
        __syncwarp();                                                          \
    } while (0)

    // Main loop: t = 1..1020 in groups of 4 (tb odd; renorm at offset 3,
    // i.e. t = 4, 8, ..., 1020). One wait per group.
    #pragma unroll 1
    for (int tb = 1; tb + 3 <= TT - 4; tb += 4) {
        asm volatile("cp.async.wait_group 11;");   // rows tb..tb+3 resident
        STEP(tb,     udup[0], udup[1], false);
        STEP(tb + 1, udup[1], udup[0], false);
        STEP(tb + 2, udup[0], udup[1], false);
        STEP(tb + 3, udup[1], udup[0], true);
    }
    // Epilogue: t = 1021, 1022, 1023 (all groups already complete)
    asm volatile("cp.async.wait_group 0;");
    STEP(TT - 3, udup[0], udup[1], false);
    STEP(TT - 2, udup[1], udup[0], false);
    STEP(TT - 1, udup[0], udup[1], false);
    #undef STEP

    // ---- finalize: logZ = (log2(sum_j u_j * expEnd_j) + credit) * ln2 ----
    float lo, hi; upk2(res, lo, hi);
    float s = (lane < 24) ? (lo * eEnd0 + hi * eEnd1) : 0.f;
    #pragma unroll
    for (int o = 16; o > 0; o >>= 1) s += __shfl_down_sync(0xFFFFFFFFu, s, o);
    if (lane == 0) g_fwd[b] = (lg2f(s) + (float)iA) * LN2;
}

// ---------------------------------------------------------------------------
// Gold score kernel: one block per batch element.
// ---------------------------------------------------------------------------
__global__ __launch_bounds__(256, 4) void crf_gold_kernel(
    const float* __restrict__ em, const int* __restrict__ labels,
    const int* __restrict__ mask, const float* __restrict__ trans,
    const float* __restrict__ startt, const float* __restrict__ endt)
{
    __shared__ float red[256];
    __shared__ int   redc[256];
    const int b = blockIdx.x;
    const int tid = threadIdx.x;

    float acc = 0.f;
    int cnt = 0;
    for (int t = tid; t < TT; t += 256) {
        int l = labels[b * TT + t];
        int m = mask[b * TT + t];
        cnt += m;
        float e = em[((size_t)(b * TT) + t) * L + l];
        if (t == 0) {
            acc += startt[l] + e;
        } else {
            int lp = labels[b * TT + t - 1];
            acc += (e + trans[l * L + lp]) * (float)m;
        }
    }
    red[tid] = acc; redc[tid] = cnt;
    __syncthreads();
    for (int s = 128; s > 0; s >>= 1) {
        if (tid < s) { red[tid] += red[tid + s]; redc[tid] += redc[tid + s]; }
        __syncthreads();
    }
    if (tid == 0) {
        int len = redc[0] - 1;
        int last = labels[b * TT + len];
        g_gold[b] = red[0] + endt[last];
    }
}

// ---------------------------------------------------------------------------
// Final reduction: mean(fwd - gold)
// ---------------------------------------------------------------------------
__global__ __launch_bounds__(512, 1) void crf_final_kernel(float* __restrict__ out)
{
    __shared__ float red[512];
    int tid = threadIdx.x;
    red[tid] = g_fwd[tid] - g_gold[tid];
    __syncthreads();
    for (int s = 256; s > 0; s >>= 1) {
        if (tid < s) red[tid] += red[tid + s];
        __syncthreads();
    }
    if (tid == 0) out[0] = red[0] * (1.0f / (float)B);
}

extern "C" void kernel_launch(void* const* d_in, const int* in_sizes, int n_in,
                              void* d_out, int out_size)
{
    const float* em     = (const float*)d_in[0];
    const int*   labels = (const int*)  d_in[1];
    const int*   mask   = (const int*)  d_in[2];
    const float* trans  = (const float*)d_in[3];
    const float* startt = (const float*)d_in[4];
    const float* endt   = (const float*)d_in[5];
    float* out = (float*)d_out;

    crf_fwd_kernel<<<B, 32>>>(em, mask, trans, startt, endt);
    crf_gold_kernel<<<B, 256>>>(em, labels, mask, trans, startt, endt);
    crf_final_kernel<<<1, 512>>>(out);
}